// round 2
// baseline (speedup 1.0000x reference)
#include <cuda_runtime.h>
#include <cuda_bf16.h>
#include <cstdint>

// ---------------------------------------------------------------------------
// Problem constants (fixed by the reference setup)
// ---------------------------------------------------------------------------
#define NB      2
#define LQ      19560
#define DMODEL  256
#define NHEADS  8
#define NLEV    4
#define NPTS    4
#define HDIM    32          // DMODEL / NHEADS
#define NROWS   (NB * LQ)   // 39120

// ---------------------------------------------------------------------------
// Device scratch (static allocation — no cudaMalloc allowed)
// ---------------------------------------------------------------------------
__device__ float g_value0[NROWS * DMODEL];   // (N,Len,8,32)
__device__ float g_value1[NROWS * DMODEL];
__device__ float g_off0[NROWS * DMODEL];     // (N,Lq,8,4,4,2)
__device__ float g_off1[NROWS * DMODEL];
__device__ float g_aw0[NROWS * 128];         // (N,Lq,8,16) -> softmaxed in-place
__device__ float g_aw1[NROWS * 128];
__device__ float g_d0[NROWS * DMODEL];       // deform-attn outputs
__device__ float g_d1[NROWS * DMODEL];
__device__ float g_Wf0[DMODEL * DMODEL];     // W_o @ W_agg_top
__device__ float g_Wf1[DMODEL * DMODEL];     // W_o @ W_agg_bot
__device__ float g_bf[DMODEL];               // fused bias

// ---------------------------------------------------------------------------
// Generic tiled SGEMM:  C[M,N] = (acc? C : 0) + A[M,K] @ B[K,N] (+ bias[N])
// BM=128, BN=64, BK=16, 256 threads, 8x4 microtile.
// Requires: K % 16 == 0, N % 64 == 0, A/B 16B-aligned.
// ---------------------------------------------------------------------------
#define BM 128
#define BN 64
#define BK 16

__global__ __launch_bounds__(256) void sgemm_kernel(
    const float* __restrict__ A, const float* __restrict__ B,
    const float* __restrict__ bias, float* __restrict__ C,
    int M, int K, int N, int accumulate)
{
    __shared__ float As[BK][BM];   // transposed: As[k][m]
    __shared__ float Bs[BK][BN];

    const int tid = threadIdx.x;
    const int tx = tid & 15;       // 0..15 -> 4 cols each
    const int ty = tid >> 4;       // 0..15 -> 8 rows each
    const int block_row = blockIdx.y * BM;
    const int block_col = blockIdx.x * BN;

    float acc[8][4];
#pragma unroll
    for (int i = 0; i < 8; i++)
#pragma unroll
        for (int j = 0; j < 4; j++) acc[i][j] = 0.f;

    for (int k0 = 0; k0 < K; k0 += BK) {
        // --- load A tile (128x16) : 512 float4, 2 per thread, transpose into As
#pragma unroll
        for (int i = 0; i < 2; i++) {
            int idx = tid + i * 256;
            int r = idx >> 2;          // 0..127
            int kv = idx & 3;          // float4 index within the 16-wide row
            int grow = block_row + r;
            float4 v = make_float4(0.f, 0.f, 0.f, 0.f);
            if (grow < M)
                v = *(const float4*)&A[(size_t)grow * K + k0 + kv * 4];
            As[kv * 4 + 0][r] = v.x;
            As[kv * 4 + 1][r] = v.y;
            As[kv * 4 + 2][r] = v.z;
            As[kv * 4 + 3][r] = v.w;
        }
        // --- load B tile (16x64) : 256 float4, 1 per thread
        {
            int r = tid >> 4;          // 0..15
            int cv = tid & 15;         // 0..15
            float4 v = *(const float4*)&B[(size_t)(k0 + r) * N + block_col + cv * 4];
            *(float4*)&Bs[r][cv * 4] = v;
        }
        __syncthreads();

#pragma unroll
        for (int kk = 0; kk < BK; kk++) {
            float4 a0 = *(const float4*)&As[kk][ty * 8];
            float4 a1 = *(const float4*)&As[kk][ty * 8 + 4];
            float4 b0 = *(const float4*)&Bs[kk][tx * 4];
            float ar[8] = {a0.x, a0.y, a0.z, a0.w, a1.x, a1.y, a1.z, a1.w};
            float br[4] = {b0.x, b0.y, b0.z, b0.w};
#pragma unroll
            for (int i = 0; i < 8; i++)
#pragma unroll
                for (int j = 0; j < 4; j++)
                    acc[i][j] = fmaf(ar[i], br[j], acc[i][j]);
        }
        __syncthreads();
    }

    // --- epilogue
#pragma unroll
    for (int i = 0; i < 8; i++) {
        int grow = block_row + ty * 8 + i;
        if (grow < M) {
#pragma unroll
            for (int j = 0; j < 4; j++) {
                int gcol = block_col + tx * 4 + j;
                float v = acc[i][j];
                if (bias) v += bias[gcol];
                size_t o = (size_t)grow * N + gcol;
                if (accumulate) v += C[o];
                C[o] = v;
            }
        }
    }
}

// ---------------------------------------------------------------------------
// Fused bias:  bf[j] = b_agg[j] + sum_m b_o[m] * (W_agg[m][j] + W_agg[m+256][j])
// ---------------------------------------------------------------------------
__global__ void fuse_bias_kernel(const float* __restrict__ b_o,
                                 const float* __restrict__ b_agg,
                                 const float* __restrict__ W_agg,
                                 float* __restrict__ bf)
{
    int j = threadIdx.x;  // 256 threads
    float s = b_agg[j];
    for (int m = 0; m < DMODEL; m++)
        s += b_o[m] * (W_agg[(size_t)m * DMODEL + j] +
                       W_agg[(size_t)(m + DMODEL) * DMODEL + j]);
    bf[j] = s;
}

// ---------------------------------------------------------------------------
// Joint softmax over 32 = concat(aw0[16], aw1[16]) per (n,q,h); in-place.
// One thread per (n,q,h).
// ---------------------------------------------------------------------------
__global__ void softmax_kernel(float* __restrict__ aw0, float* __restrict__ aw1,
                               int total)
{
    int t = blockIdx.x * blockDim.x + threadIdx.x;
    if (t >= total) return;
    float4* p0 = (float4*)(aw0 + (size_t)t * 16);
    float4* p1 = (float4*)(aw1 + (size_t)t * 16);
    float v[32];
    float4 r;
#pragma unroll
    for (int i = 0; i < 4; i++) {
        r = p0[i]; v[i*4+0]=r.x; v[i*4+1]=r.y; v[i*4+2]=r.z; v[i*4+3]=r.w;
    }
#pragma unroll
    for (int i = 0; i < 4; i++) {
        r = p1[i]; v[16+i*4+0]=r.x; v[16+i*4+1]=r.y; v[16+i*4+2]=r.z; v[16+i*4+3]=r.w;
    }
    float mx = v[0];
#pragma unroll
    for (int i = 1; i < 32; i++) mx = fmaxf(mx, v[i]);
    float sum = 0.f;
#pragma unroll
    for (int i = 0; i < 32; i++) { v[i] = expf(v[i] - mx); sum += v[i]; }
    float inv = 1.f / sum;
#pragma unroll
    for (int i = 0; i < 32; i++) v[i] *= inv;
#pragma unroll
    for (int i = 0; i < 4; i++)
        p0[i] = make_float4(v[i*4+0], v[i*4+1], v[i*4+2], v[i*4+3]);
#pragma unroll
    for (int i = 0; i < 4; i++)
        p1[i] = make_float4(v[16+i*4+0], v[16+i*4+1], v[16+i*4+2], v[16+i*4+3]);
}

// ---------------------------------------------------------------------------
// Deformable-attention sampling. One warp per (n,q,h); lane = channel.
// value:(N,Len,8,32)  ref:(N,Lq,4,2)  off:(N,Lq,8,4,4,2)  attn:(N,Lq,8,16)
// out:(N,Lq,256)
// ---------------------------------------------------------------------------
__global__ __launch_bounds__(256) void sample_kernel(
    const float* __restrict__ value, const float* __restrict__ ref,
    const float* __restrict__ off, const float* __restrict__ attn,
    const int* __restrict__ shapes, const int* __restrict__ starts,
    float* __restrict__ out)
{
    int gwarp = (blockIdx.x * blockDim.x + threadIdx.x) >> 5;
    int lane = threadIdx.x & 31;
    if (gwarp >= NROWS * NHEADS) return;

    int h = gwarp & 7;
    int nq = gwarp >> 3;                 // n*LQ + q
    int n = nq / LQ;

    // per-warp metadata (lane-parallel loads, broadcast via shfl)
    float my_off  = off[((size_t)nq * NHEADS + h) * 32 + lane];
    float my_attn = (lane < 16) ? attn[((size_t)nq * NHEADS + h) * 16 + lane] : 0.f;
    float my_ref  = (lane < 8)  ? ref[(size_t)nq * 8 + lane] : 0.f;

    float acc = 0.f;

#pragma unroll
    for (int l = 0; l < NLEV; l++) {
        int H = shapes[l * 2 + 0];
        int W = shapes[l * 2 + 1];
        int s = starts[l];
        float fW = (float)W, fH = (float)H;
        float rx = __shfl_sync(0xFFFFFFFFu, my_ref, l * 2 + 0);
        float ry = __shfl_sync(0xFFFFFFFFu, my_ref, l * 2 + 1);
        const float* vbase =
            value + (((size_t)n * LQ + s) * NHEADS + h) * HDIM + lane;

#pragma unroll
        for (int p = 0; p < NPTS; p++) {
            int sp = l * 4 + p;
            float ox = __shfl_sync(0xFFFFFFFFu, my_off, sp * 2 + 0);
            float oy = __shfl_sync(0xFFFFFFFFu, my_off, sp * 2 + 1);
            float a  = __shfl_sync(0xFFFFFFFFu, my_attn, sp);

            // match reference arithmetic order exactly:
            // loc = ref + off / (W,H);  x = loc.x*W - 0.5;  y = loc.y*H - 0.5
            float x = (rx + ox / fW) * fW - 0.5f;
            float y = (ry + oy / fH) * fH - 0.5f;
            float x0f = floorf(x), y0f = floorf(y);
            int x0 = (int)x0f, y0 = (int)y0f;
            float lx = x - x0f, ly = y - y0f;
            float hx = 1.f - lx, hy = 1.f - ly;

            float smp = 0.f;
            bool xin0 = (x0 >= 0) & (x0 < W);
            bool xin1 = (x0 + 1 >= 0) & (x0 + 1 < W);
            bool yin0 = (y0 >= 0) & (y0 < H);
            bool yin1 = (y0 + 1 >= 0) & (y0 + 1 < H);
            if (xin0 & yin0) smp = fmaf(hy * hx, vbase[(size_t)(y0 * W + x0) * DMODEL], smp);
            if (xin1 & yin0) smp = fmaf(hy * lx, vbase[(size_t)(y0 * W + x0 + 1) * DMODEL], smp);
            if (xin0 & yin1) smp = fmaf(ly * hx, vbase[(size_t)((y0 + 1) * W + x0) * DMODEL], smp);
            if (xin1 & yin1) smp = fmaf(ly * lx, vbase[(size_t)((y0 + 1) * W + x0 + 1) * DMODEL], smp);
            acc = fmaf(a, smp, acc);
        }
    }

    out[(size_t)nq * DMODEL + h * HDIM + lane] = acc;
}

// ---------------------------------------------------------------------------
// Launcher
// ---------------------------------------------------------------------------
extern "C" void kernel_launch(void* const* d_in, const int* in_sizes, int n_in,
                              void* d_out, int out_size)
{
    const float* q0     = (const float*)d_in[0];
    const float* q1     = (const float*)d_in[1];
    const float* ref    = (const float*)d_in[2];
    const float* flat0  = (const float*)d_in[3];
    const float* flat1  = (const float*)d_in[4];
    const int*   shapes = (const int*)  d_in[5];
    const int*   starts = (const int*)  d_in[6];
    const float* W_so   = (const float*)d_in[7];
    const float* b_so   = (const float*)d_in[8];
    const float* W_aw   = (const float*)d_in[9];
    const float* b_aw   = (const float*)d_in[10];
    const float* W_v    = (const float*)d_in[11];
    const float* b_v    = (const float*)d_in[12];
    const float* W_o    = (const float*)d_in[13];
    const float* b_o    = (const float*)d_in[14];
    const float* W_agg  = (const float*)d_in[15];
    const float* b_agg  = (const float*)d_in[16];
    float* out = (float*)d_out;

    float *value0, *value1, *off0, *off1, *aw0, *aw1, *dd0, *dd1, *Wf0, *Wf1, *bf;
    cudaGetSymbolAddress((void**)&value0, g_value0);
    cudaGetSymbolAddress((void**)&value1, g_value1);
    cudaGetSymbolAddress((void**)&off0, g_off0);
    cudaGetSymbolAddress((void**)&off1, g_off1);
    cudaGetSymbolAddress((void**)&aw0, g_aw0);
    cudaGetSymbolAddress((void**)&aw1, g_aw1);
    cudaGetSymbolAddress((void**)&dd0, g_d0);
    cudaGetSymbolAddress((void**)&dd1, g_d1);
    cudaGetSymbolAddress((void**)&Wf0, g_Wf0);
    cudaGetSymbolAddress((void**)&Wf1, g_Wf1);
    cudaGetSymbolAddress((void**)&bf, g_bf);

    dim3 blk(256);
    dim3 grid_big((DMODEL + BN - 1) / BN, (NROWS + BM - 1) / BM);   // (4, 306)
    dim3 grid_aw((128 + BN - 1) / BN, (NROWS + BM - 1) / BM);      // (2, 306)
    dim3 grid_wf((DMODEL + BN - 1) / BN, (DMODEL + BM - 1) / BM);  // (4, 2)

    // Fused projection matrices: Wf_i = W_o @ W_agg[i*256:(i+1)*256, :]
    sgemm_kernel<<<grid_wf, blk>>>(W_o, W_agg,                 nullptr, Wf0, DMODEL, DMODEL, DMODEL, 0);
    sgemm_kernel<<<grid_wf, blk>>>(W_o, W_agg + DMODEL*DMODEL, nullptr, Wf1, DMODEL, DMODEL, DMODEL, 0);
    fuse_bias_kernel<<<1, DMODEL>>>(b_o, b_agg, W_agg, bf);

    // value / offsets / attention-weight projections
    sgemm_kernel<<<grid_big, blk>>>(flat0, W_v, b_v, value0, NROWS, DMODEL, DMODEL, 0);
    sgemm_kernel<<<grid_big, blk>>>(flat1, W_v, b_v, value1, NROWS, DMODEL, DMODEL, 0);
    sgemm_kernel<<<grid_big, blk>>>(q0, W_so, b_so, off0, NROWS, DMODEL, DMODEL, 0);
    sgemm_kernel<<<grid_big, blk>>>(q1, W_so, b_so, off1, NROWS, DMODEL, DMODEL, 0);
    sgemm_kernel<<<grid_aw,  blk>>>(q0, W_aw, b_aw, aw0, NROWS, DMODEL, 128, 0);
    sgemm_kernel<<<grid_aw,  blk>>>(q1, W_aw, b_aw, aw1, NROWS, DMODEL, 128, 0);

    // joint softmax over 32 (in-place)
    {
        int total = NROWS * NHEADS;
        int blocks = (total + 255) / 256;
        softmax_kernel<<<blocks, 256>>>(aw0, aw1, total);
    }

    // deformable sampling (one warp per (n,q,h))
    {
        int warps = NROWS * NHEADS;
        int blocks = (warps * 32 + 255) / 256;
        sample_kernel<<<blocks, 256>>>(value0, ref, off0, aw0, shapes, starts, dd0);
        sample_kernel<<<blocks, 256>>>(value1, ref, off1, aw1, shapes, starts, dd1);
    }

    // fused output projection: out = d0@Wf0 + bf; out += d1@Wf1
    sgemm_kernel<<<grid_big, blk>>>(dd0, Wf0, bf,      out, NROWS, DMODEL, DMODEL, 0);
    sgemm_kernel<<<grid_big, blk>>>(dd1, Wf1, nullptr, out, NROWS, DMODEL, DMODEL, 1);

    (void)in_sizes; (void)n_in; (void)out_size;
}

// round 5
// speedup vs baseline: 1.1408x; 1.1408x over previous
#include <cuda_runtime.h>
#include <cuda_fp16.h>
#include <mma.h>
#include <cstdint>

using namespace nvcuda;

// ---------------------------------------------------------------------------
// Problem constants
// ---------------------------------------------------------------------------
#define NB      2
#define LQ      19560
#define DMODEL  256
#define NHEADS  8
#define NLEV    4
#define NPTS    4
#define HDIM    32
#define NROWS   (NB * LQ)   // 39120
#define KSTRIDE 256

// ---------------------------------------------------------------------------
// Device scratch (static; no cudaMalloc allowed)
// ---------------------------------------------------------------------------
__device__ __align__(256) __half g_value0[NROWS * DMODEL];
__device__ __align__(256) __half g_value1[NROWS * DMODEL];
__device__ __align__(256) float  g_off0[NROWS * DMODEL];
__device__ __align__(256) float  g_off1[NROWS * DMODEL];
__device__ __align__(256) float  g_aw0[NROWS * 128];
__device__ __align__(256) float  g_aw1[NROWS * 128];
__device__ __align__(256) float  g_d0[NROWS * DMODEL];
__device__ __align__(256) float  g_d1[NROWS * DMODEL];
__device__ __align__(256) float  g_Wt_v[DMODEL * DMODEL];    // W_v^T (K-major)
__device__ __align__(256) float  g_Wt_aw[128 * DMODEL];      // W_aw^T
__device__ __align__(256) float  g_Wf0[DMODEL * DMODEL];     // W_o @ W_agg_top
__device__ __align__(256) float  g_Wf1[DMODEL * DMODEL];
__device__ __align__(256) float  g_Wf0t[DMODEL * DMODEL];
__device__ __align__(256) float  g_Wf1t[DMODEL * DMODEL];
__device__ __align__(256) float  g_bf[DMODEL];

// ---------------------------------------------------------------------------
// FFMA SGEMM (proven in R2): C[M,N] = A[M,K] @ B[K,N] (+bias). B row-major [K,N].
// ---------------------------------------------------------------------------
#define BM 128
#define BN 64
#define BK 16

__global__ __launch_bounds__(256) void sgemm_kernel(
    const float* __restrict__ A, const float* __restrict__ B,
    const float* __restrict__ bias, float* __restrict__ C,
    int M, int K, int N)
{
    __shared__ float As[BK][BM];
    __shared__ float Bs[BK][BN];

    const int tid = threadIdx.x;
    const int tx = tid & 15;
    const int ty = tid >> 4;
    const int block_row = blockIdx.y * BM;
    const int block_col = blockIdx.x * BN;

    float acc[8][4];
#pragma unroll
    for (int i = 0; i < 8; i++)
#pragma unroll
        for (int j = 0; j < 4; j++) acc[i][j] = 0.f;

    for (int k0 = 0; k0 < K; k0 += BK) {
#pragma unroll
        for (int i = 0; i < 2; i++) {
            int idx = tid + i * 256;
            int r = idx >> 2;
            int kv = idx & 3;
            int grow = block_row + r;
            float4 v = make_float4(0.f, 0.f, 0.f, 0.f);
            if (grow < M)
                v = *(const float4*)&A[(size_t)grow * K + k0 + kv * 4];
            As[kv * 4 + 0][r] = v.x;
            As[kv * 4 + 1][r] = v.y;
            As[kv * 4 + 2][r] = v.z;
            As[kv * 4 + 3][r] = v.w;
        }
        {
            int r = tid >> 4;
            int cv = tid & 15;
            float4 v = *(const float4*)&B[(size_t)(k0 + r) * N + block_col + cv * 4];
            *(float4*)&Bs[r][cv * 4] = v;
        }
        __syncthreads();

#pragma unroll
        for (int kk = 0; kk < BK; kk++) {
            float4 a0 = *(const float4*)&As[kk][ty * 8];
            float4 a1 = *(const float4*)&As[kk][ty * 8 + 4];
            float4 b0 = *(const float4*)&Bs[kk][tx * 4];
            float ar[8] = {a0.x, a0.y, a0.z, a0.w, a1.x, a1.y, a1.z, a1.w};
            float br[4] = {b0.x, b0.y, b0.z, b0.w};
#pragma unroll
            for (int i = 0; i < 8; i++)
#pragma unroll
                for (int j = 0; j < 4; j++)
                    acc[i][j] = fmaf(ar[i], br[j], acc[i][j]);
        }
        __syncthreads();
    }

#pragma unroll
    for (int i = 0; i < 8; i++) {
        int grow = block_row + ty * 8 + i;
        if (grow < M) {
#pragma unroll
            for (int j = 0; j < 4; j++) {
                int gcol = block_col + tx * 4 + j;
                float v = acc[i][j];
                if (bias) v += bias[gcol];
                C[(size_t)grow * N + gcol] = v;
            }
        }
    }
}

// ---------------------------------------------------------------------------
// wmma tf32 GEMM.  C[M,NT] = concat_K(A0,A1) @ concat_K(B0t,B1t) + bias
//   A row-major [M,256] per source; Bt K-major [NT,256] per source.
//   CTA tile 128x64, 8 warps of 32x32, K chunked by 32.  EPI: 0=f32, 1=f16.
// ---------------------------------------------------------------------------
template <int NT, int EPI>
__global__ __launch_bounds__(256) void gemm_wmma(
    const float* __restrict__ A0, const float* __restrict__ A1, int chunksA,
    const float* __restrict__ B0, const float* __restrict__ B1, int chunksTot,
    const float* __restrict__ bias, void* __restrict__ Cout, int M)
{
    __shared__ union {
        struct { float A[128][40]; float B[64][40]; } ld;   // 30720 B
        float C[128][72];                                   // 36864 B
    } sm;

    const int tid = threadIdx.x;
    const int wid = tid >> 5;
    const int wm = (wid & 3) * 32;       // warp m-offset (4 m-warps)
    const int wn = (wid >> 2) * 32;      // warp n-offset (2 n-warps)
    const int mbase = blockIdx.y * 128;
    const int ncol0 = blockIdx.x * 64;

    wmma::fragment<wmma::accumulator, 16, 16, 8, float> acc[2][2];
#pragma unroll
    for (int i = 0; i < 2; i++)
#pragma unroll
        for (int j = 0; j < 2; j++) wmma::fill_fragment(acc[i][j], 0.f);

    for (int c = 0; c < chunksTot; ++c) {
        const float* Ap; const float* Bp; int kloc;
        if (c < chunksA) { Ap = A0; Bp = B0; kloc = c * 32; }
        else             { Ap = A1; Bp = B1; kloc = (c - chunksA) * 32; }

        // A tile: 128 x 32 f32 (1024 float4)
#pragma unroll
        for (int i = tid; i < 1024; i += 256) {
            int row = i >> 3, j = i & 7;
            int grow = mbase + row;
            float4 v = make_float4(0.f, 0.f, 0.f, 0.f);
            if (grow < M) v = *(const float4*)&Ap[(size_t)grow * KSTRIDE + kloc + j * 4];
            *(float4*)&sm.ld.A[row][j * 4] = v;
        }
        // B tile: 64 x 32 f32 (512 float4), Bt K-major rows
#pragma unroll
        for (int i = tid; i < 512; i += 256) {
            int row = i >> 3, j = i & 7;
            float4 v = *(const float4*)&Bp[(size_t)(ncol0 + row) * KSTRIDE + kloc + j * 4];
            *(float4*)&sm.ld.B[row][j * 4] = v;
        }
        __syncthreads();

#pragma unroll
        for (int kk = 0; kk < 32; kk += 8) {
            wmma::fragment<wmma::matrix_a, 16, 16, 8, wmma::precision::tf32, wmma::row_major> a0, a1;
            wmma::fragment<wmma::matrix_b, 16, 16, 8, wmma::precision::tf32, wmma::col_major> b0, b1;
            wmma::load_matrix_sync(a0, &sm.ld.A[wm][kk], 40);
            wmma::load_matrix_sync(a1, &sm.ld.A[wm + 16][kk], 40);
            wmma::load_matrix_sync(b0, &sm.ld.B[wn][kk], 40);
            wmma::load_matrix_sync(b1, &sm.ld.B[wn + 16][kk], 40);
#pragma unroll
            for (int e = 0; e < a0.num_elements; e++) {
                a0.x[e] = wmma::__float_to_tf32(a0.x[e]);
                a1.x[e] = wmma::__float_to_tf32(a1.x[e]);
            }
#pragma unroll
            for (int e = 0; e < b0.num_elements; e++) {
                b0.x[e] = wmma::__float_to_tf32(b0.x[e]);
                b1.x[e] = wmma::__float_to_tf32(b1.x[e]);
            }
            wmma::mma_sync(acc[0][0], a0, b0, acc[0][0]);
            wmma::mma_sync(acc[0][1], a0, b1, acc[0][1]);
            wmma::mma_sync(acc[1][0], a1, b0, acc[1][0]);
            wmma::mma_sync(acc[1][1], a1, b1, acc[1][1]);
        }
        __syncthreads();
    }

    // epilogue: stage via SMEM, add bias, write f32 or f16
    wmma::store_matrix_sync(&sm.C[wm][wn],           acc[0][0], 72, wmma::mem_row_major);
    wmma::store_matrix_sync(&sm.C[wm][wn + 16],      acc[0][1], 72, wmma::mem_row_major);
    wmma::store_matrix_sync(&sm.C[wm + 16][wn],      acc[1][0], 72, wmma::mem_row_major);
    wmma::store_matrix_sync(&sm.C[wm + 16][wn + 16], acc[1][1], 72, wmma::mem_row_major);
    __syncthreads();

#pragma unroll
    for (int i = tid; i < 128 * 16; i += 256) {
        int row = i >> 4, j = i & 15;
        int grow = mbase + row;
        if (grow < M) {
            int col = ncol0 + j * 4;
            float4 v = *(const float4*)&sm.C[row][j * 4];
            if (bias) {
                v.x += bias[col + 0]; v.y += bias[col + 1];
                v.z += bias[col + 2]; v.w += bias[col + 3];
            }
            if (EPI == 0) {
                *(float4*)((float*)Cout + (size_t)grow * NT + col) = v;
            } else {
                __half* Cp = (__half*)Cout + (size_t)grow * NT + col;
                *(__half2*)(Cp)     = __floats2half2_rn(v.x, v.y);
                *(__half2*)(Cp + 2) = __floats2half2_rn(v.z, v.w);
            }
        }
    }
}

// ---------------------------------------------------------------------------
// Generic transpose: out[C, R] = in[R, C]^T
// ---------------------------------------------------------------------------
__global__ void transpose_kernel(const float* __restrict__ in, float* __restrict__ out,
                                 int R, int C)
{
    __shared__ float t[32][33];
    int bx = blockIdx.x * 32, by = blockIdx.y * 32;
    int x = bx + threadIdx.x;
#pragma unroll
    for (int i = 0; i < 32; i += 8) {
        int y = by + threadIdx.y + i;
        if (x < C && y < R) t[threadIdx.y + i][threadIdx.x] = in[(size_t)y * C + x];
    }
    __syncthreads();
    int x2 = by + threadIdx.x;
#pragma unroll
    for (int i = 0; i < 32; i += 8) {
        int y2 = bx + threadIdx.y + i;
        if (x2 < R && y2 < C) out[(size_t)y2 * R + x2] = t[threadIdx.x][threadIdx.y + i];
    }
}

// ---------------------------------------------------------------------------
// bf[j] = b_agg[j] + sum_m b_o[m] * (W_agg[m][j] + W_agg[m+256][j])
// ---------------------------------------------------------------------------
__global__ void fuse_bias_kernel(const float* __restrict__ b_o,
                                 const float* __restrict__ b_agg,
                                 const float* __restrict__ W_agg,
                                 float* __restrict__ bf)
{
    int j = threadIdx.x;
    float s = b_agg[j];
    for (int m = 0; m < DMODEL; m++)
        s += b_o[m] * (W_agg[(size_t)m * DMODEL + j] +
                       W_agg[(size_t)(m + DMODEL) * DMODEL + j]);
    bf[j] = s;
}

// ---------------------------------------------------------------------------
// Joint softmax over 32 = concat(aw0[16], aw1[16]) per (n,q,h); in-place.
// ---------------------------------------------------------------------------
__global__ void softmax_kernel(float* __restrict__ aw0, float* __restrict__ aw1,
                               int total)
{
    int t = blockIdx.x * blockDim.x + threadIdx.x;
    if (t >= total) return;
    float4* p0 = (float4*)(aw0 + (size_t)t * 16);
    float4* p1 = (float4*)(aw1 + (size_t)t * 16);
    float v[32];
    float4 r;
#pragma unroll
    for (int i = 0; i < 4; i++) {
        r = p0[i]; v[i*4+0]=r.x; v[i*4+1]=r.y; v[i*4+2]=r.z; v[i*4+3]=r.w;
    }
#pragma unroll
    for (int i = 0; i < 4; i++) {
        r = p1[i]; v[16+i*4+0]=r.x; v[16+i*4+1]=r.y; v[16+i*4+2]=r.z; v[16+i*4+3]=r.w;
    }
    float mx = v[0];
#pragma unroll
    for (int i = 1; i < 32; i++) mx = fmaxf(mx, v[i]);
    float sum = 0.f;
#pragma unroll
    for (int i = 0; i < 32; i++) { v[i] = expf(v[i] - mx); sum += v[i]; }
    float inv = 1.f / sum;
#pragma unroll
    for (int i = 0; i < 32; i++) v[i] *= inv;
#pragma unroll
    for (int i = 0; i < 4; i++)
        p0[i] = make_float4(v[i*4+0], v[i*4+1], v[i*4+2], v[i*4+3]);
#pragma unroll
    for (int i = 0; i < 4; i++)
        p1[i] = make_float4(v[16+i*4+0], v[16+i*4+1], v[16+i*4+2], v[16+i*4+3]);
}

// ---------------------------------------------------------------------------
// Deformable sampling: one warp per (n,q,h); lane = channel; value in fp16.
// ---------------------------------------------------------------------------
__global__ __launch_bounds__(256) void sample_kernel(
    const __half* __restrict__ value, const float* __restrict__ ref,
    const float* __restrict__ off, const float* __restrict__ attn,
    const int* __restrict__ shapes, const int* __restrict__ starts,
    float* __restrict__ out)
{
    int gwarp = (blockIdx.x * blockDim.x + threadIdx.x) >> 5;
    int lane = threadIdx.x & 31;
    if (gwarp >= NROWS * NHEADS) return;

    int h = gwarp & 7;
    int nq = gwarp >> 3;
    int n = nq / LQ;

    float my_off  = off[((size_t)nq * NHEADS + h) * 32 + lane];
    float my_attn = (lane < 16) ? attn[((size_t)nq * NHEADS + h) * 16 + lane] : 0.f;
    float my_ref  = (lane < 8)  ? ref[(size_t)nq * 8 + lane] : 0.f;

    float acc = 0.f;

#pragma unroll
    for (int l = 0; l < NLEV; l++) {
        int H = shapes[l * 2 + 0];
        int W = shapes[l * 2 + 1];
        int s = starts[l];
        float fW = (float)W, fH = (float)H;
        float rx = __shfl_sync(0xFFFFFFFFu, my_ref, l * 2 + 0);
        float ry = __shfl_sync(0xFFFFFFFFu, my_ref, l * 2 + 1);
        const __half* vbase =
            value + (((size_t)n * LQ + s) * NHEADS + h) * HDIM + lane;

#pragma unroll
        for (int p = 0; p < NPTS; p++) {
            int sp = l * 4 + p;
            float ox = __shfl_sync(0xFFFFFFFFu, my_off, sp * 2 + 0);
            float oy = __shfl_sync(0xFFFFFFFFu, my_off, sp * 2 + 1);
            float a  = __shfl_sync(0xFFFFFFFFu, my_attn, sp);

            // match reference arithmetic order exactly
            float x = (rx + ox / fW) * fW - 0.5f;
            float y = (ry + oy / fH) * fH - 0.5f;
            float x0f = floorf(x), y0f = floorf(y);
            int x0 = (int)x0f, y0 = (int)y0f;
            float lx = x - x0f, ly = y - y0f;
            float hx = 1.f - lx, hy = 1.f - ly;

            float smp = 0.f;
            bool xin0 = (x0 >= 0) & (x0 < W);
            bool xin1 = (x0 + 1 >= 0) & (x0 + 1 < W);
            bool yin0 = (y0 >= 0) & (y0 < H);
            bool yin1 = (y0 + 1 >= 0) & (y0 + 1 < H);
            if (xin0 & yin0) smp = fmaf(hy * hx, __half2float(vbase[(size_t)(y0 * W + x0) * DMODEL]), smp);
            if (xin1 & yin0) smp = fmaf(hy * lx, __half2float(vbase[(size_t)(y0 * W + x0 + 1) * DMODEL]), smp);
            if (xin0 & yin1) smp = fmaf(ly * hx, __half2float(vbase[(size_t)((y0 + 1) * W + x0) * DMODEL]), smp);
            if (xin1 & yin1) smp = fmaf(ly * lx, __half2float(vbase[(size_t)((y0 + 1) * W + x0 + 1) * DMODEL]), smp);
            acc = fmaf(a, smp, acc);
        }
    }

    out[(size_t)nq * DMODEL + h * HDIM + lane] = acc;
}

// ---------------------------------------------------------------------------
// Launcher
// ---------------------------------------------------------------------------
extern "C" void kernel_launch(void* const* d_in, const int* in_sizes, int n_in,
                              void* d_out, int out_size)
{
    const float* q0     = (const float*)d_in[0];
    const float* q1     = (const float*)d_in[1];
    const float* ref    = (const float*)d_in[2];
    const float* flat0  = (const float*)d_in[3];
    const float* flat1  = (const float*)d_in[4];
    const int*   shapes = (const int*)  d_in[5];
    const int*   starts = (const int*)  d_in[6];
    const float* W_so   = (const float*)d_in[7];
    const float* b_so   = (const float*)d_in[8];
    const float* W_aw   = (const float*)d_in[9];
    const float* b_aw   = (const float*)d_in[10];
    const float* W_v    = (const float*)d_in[11];
    const float* b_v    = (const float*)d_in[12];
    const float* W_o    = (const float*)d_in[13];
    const float* b_o    = (const float*)d_in[14];
    const float* W_agg  = (const float*)d_in[15];
    const float* b_agg  = (const float*)d_in[16];
    float* out = (float*)d_out;

    __half *value0, *value1;
    float *off0, *off1, *aw0, *aw1, *dd0, *dd1;
    float *Wt_v, *Wt_aw, *Wf0, *Wf1, *Wf0t, *Wf1t, *bf;
    cudaGetSymbolAddress((void**)&value0, g_value0);
    cudaGetSymbolAddress((void**)&value1, g_value1);
    cudaGetSymbolAddress((void**)&off0, g_off0);
    cudaGetSymbolAddress((void**)&off1, g_off1);
    cudaGetSymbolAddress((void**)&aw0, g_aw0);
    cudaGetSymbolAddress((void**)&aw1, g_aw1);
    cudaGetSymbolAddress((void**)&dd0, g_d0);
    cudaGetSymbolAddress((void**)&dd1, g_d1);
    cudaGetSymbolAddress((void**)&Wt_v, g_Wt_v);
    cudaGetSymbolAddress((void**)&Wt_aw, g_Wt_aw);
    cudaGetSymbolAddress((void**)&Wf0, g_Wf0);
    cudaGetSymbolAddress((void**)&Wf1, g_Wf1);
    cudaGetSymbolAddress((void**)&Wf0t, g_Wf0t);
    cudaGetSymbolAddress((void**)&Wf1t, g_Wf1t);
    cudaGetSymbolAddress((void**)&bf, g_bf);

    dim3 blk(256);
    dim3 tblk(32, 8);

    // --- weight prep (fp32 FFMA for precision; tiny) ---
    // Wf_i = W_o @ W_agg[i*256:(i+1)*256, :]   (B row-major [K,N] = W_agg half)
    sgemm_kernel<<<dim3(4, 2), blk>>>(W_o, W_agg,               nullptr, Wf0, 256, 256, 256);
    sgemm_kernel<<<dim3(4, 2), blk>>>(W_o, W_agg + 256 * 256,   nullptr, Wf1, 256, 256, 256);
    fuse_bias_kernel<<<1, DMODEL>>>(b_o, b_agg, W_agg, bf);
    // K-major transposes for wmma B operands
    transpose_kernel<<<dim3(8, 8), tblk>>>(W_v,  Wt_v,  256, 256);
    transpose_kernel<<<dim3(4, 8), tblk>>>(W_aw, Wt_aw, 256, 128);
    transpose_kernel<<<dim3(8, 8), tblk>>>(Wf0,  Wf0t,  256, 256);
    transpose_kernel<<<dim3(8, 8), tblk>>>(Wf1,  Wf1t,  256, 256);

    const int MT = (NROWS + 127) / 128;   // 306

    // --- value projection (tf32 tensor cores, fp16 output) ---
    gemm_wmma<256, 1><<<dim3(4, MT), blk>>>(flat0, flat0, 8, Wt_v, Wt_v, 8, b_v, value0, NROWS);
    gemm_wmma<256, 1><<<dim3(4, MT), blk>>>(flat1, flat1, 8, Wt_v, Wt_v, 8, b_v, value1, NROWS);

    // --- offset projection (exact fp32 FFMA — sampling positions are
    //     error-amplifying, keep them bit-faithful) ---
    sgemm_kernel<<<dim3(4, MT), blk>>>(q0, W_so, b_so, off0, NROWS, 256, 256);
    sgemm_kernel<<<dim3(4, MT), blk>>>(q1, W_so, b_so, off1, NROWS, 256, 256);

    // --- attention-weight projection (tf32; softmax damps the error) ---
    gemm_wmma<128, 0><<<dim3(2, MT), blk>>>(q0, q0, 8, Wt_aw, Wt_aw, 8, b_aw, aw0, NROWS);
    gemm_wmma<128, 0><<<dim3(2, MT), blk>>>(q1, q1, 8, Wt_aw, Wt_aw, 8, b_aw, aw1, NROWS);

    // --- joint softmax over 32 ---
    {
        int total = NROWS * NHEADS;
        softmax_kernel<<<(total + 255) / 256, 256>>>(aw0, aw1, total);
    }

    // --- deformable sampling (fp16 values halve gather traffic) ---
    {
        int warps = NROWS * NHEADS;
        int blocks = (warps * 32 + 255) / 256;
        sample_kernel<<<blocks, 256>>>(value0, ref, off0, aw0, shapes, starts, dd0);
        sample_kernel<<<blocks, 256>>>(value1, ref, off1, aw1, shapes, starts, dd1);
    }

    // --- fused output projection: out = d0@Wf0t + d1@Wf1t + bf  (K=512) ---
    gemm_wmma<256, 0><<<dim3(4, MT), blk>>>(dd0, dd1, 8, Wf0t, Wf1t, 16, bf, out, NROWS);

    (void)in_sizes; (void)n_in; (void)out_size;
}

// round 7
// speedup vs baseline: 1.5063x; 1.3204x over previous
#include <cuda_runtime.h>
#include <cuda_fp16.h>
#include <mma.h>
#include <cstdint>

using namespace nvcuda;

// ---------------------------------------------------------------------------
// Problem constants
// ---------------------------------------------------------------------------
#define NB      2
#define LQ      19560
#define DMODEL  256
#define NHEADS  8
#define NLEV    4
#define NPTS    4
#define HDIM    32
#define NROWS   (NB * LQ)   // 39120
#define KSTRIDE 256

// ---------------------------------------------------------------------------
// Device scratch (static; no cudaMalloc allowed)
// ---------------------------------------------------------------------------
__device__ __align__(256) __half g_value0[NROWS * DMODEL];
__device__ __align__(256) __half g_value1[NROWS * DMODEL];
__device__ __align__(256) float  g_off0[NROWS * DMODEL];
__device__ __align__(256) float  g_off1[NROWS * DMODEL];
__device__ __align__(256) float  g_aw0[NROWS * 128];
__device__ __align__(256) float  g_aw1[NROWS * 128];
__device__ __align__(256) float  g_d0[NROWS * DMODEL];
__device__ __align__(256) float  g_d1[NROWS * DMODEL];
__device__ __align__(256) float  g_Wf0[DMODEL * DMODEL];     // W_o @ W_agg_top (f32)
__device__ __align__(256) float  g_Wf1[DMODEL * DMODEL];
__device__ __align__(256) __half g_Whv[DMODEL * DMODEL];     // half, K-major
__device__ __align__(256) __half g_Whso[DMODEL * DMODEL];
__device__ __align__(256) __half g_Whaw[128 * DMODEL];
__device__ __align__(256) __half g_Whf0[DMODEL * DMODEL];
__device__ __align__(256) __half g_Whf1[DMODEL * DMODEL];
__device__ __align__(256) float  g_bf[DMODEL];

// ---------------------------------------------------------------------------
// FFMA SGEMM (for tiny weight-prep GEMMs only)
// ---------------------------------------------------------------------------
#define BM 128
#define BN 64
#define BK 16

__global__ __launch_bounds__(256) void sgemm_kernel(
    const float* __restrict__ A, const float* __restrict__ B,
    const float* __restrict__ bias, float* __restrict__ C,
    int M, int K, int N)
{
    __shared__ float As[BK][BM];
    __shared__ float Bs[BK][BN];

    const int tid = threadIdx.x;
    const int tx = tid & 15;
    const int ty = tid >> 4;
    const int block_row = blockIdx.y * BM;
    const int block_col = blockIdx.x * BN;

    float acc[8][4];
#pragma unroll
    for (int i = 0; i < 8; i++)
#pragma unroll
        for (int j = 0; j < 4; j++) acc[i][j] = 0.f;

    for (int k0 = 0; k0 < K; k0 += BK) {
#pragma unroll
        for (int i = 0; i < 2; i++) {
            int idx = tid + i * 256;
            int r = idx >> 2;
            int kv = idx & 3;
            int grow = block_row + r;
            float4 v = make_float4(0.f, 0.f, 0.f, 0.f);
            if (grow < M)
                v = *(const float4*)&A[(size_t)grow * K + k0 + kv * 4];
            As[kv * 4 + 0][r] = v.x;
            As[kv * 4 + 1][r] = v.y;
            As[kv * 4 + 2][r] = v.z;
            As[kv * 4 + 3][r] = v.w;
        }
        {
            int r = tid >> 4;
            int cv = tid & 15;
            float4 v = *(const float4*)&B[(size_t)(k0 + r) * N + block_col + cv * 4];
            *(float4*)&Bs[r][cv * 4] = v;
        }
        __syncthreads();

#pragma unroll
        for (int kk = 0; kk < BK; kk++) {
            float4 a0 = *(const float4*)&As[kk][ty * 8];
            float4 a1 = *(const float4*)&As[kk][ty * 8 + 4];
            float4 b0 = *(const float4*)&Bs[kk][tx * 4];
            float ar[8] = {a0.x, a0.y, a0.z, a0.w, a1.x, a1.y, a1.z, a1.w};
            float br[4] = {b0.x, b0.y, b0.z, b0.w};
#pragma unroll
            for (int i = 0; i < 8; i++)
#pragma unroll
                for (int j = 0; j < 4; j++)
                    acc[i][j] = fmaf(ar[i], br[j], acc[i][j]);
        }
        __syncthreads();
    }

#pragma unroll
    for (int i = 0; i < 8; i++) {
        int grow = block_row + ty * 8 + i;
        if (grow < M) {
#pragma unroll
            for (int j = 0; j < 4; j++) {
                int gcol = block_col + tx * 4 + j;
                float v = acc[i][j];
                if (bias) v += bias[gcol];
                C[(size_t)grow * N + gcol] = v;
            }
        }
    }
}

// ---------------------------------------------------------------------------
// fp16 wmma GEMM (m16n16k16, fp32 accum).
//   C[M,NT] = concat_K(A0,A1) @ concat_K(B0h,B1h) + bias
//   A fp32 row-major [M,256] per source (converted to half on SMEM load);
//   Bh half K-major [NT,256] per source.
//   CTA tile 128x64, 8 warps of 32x32, K chunked by 64.  EPI: 0=f32, 1=f16.
// ---------------------------------------------------------------------------
template <int NT, int EPI>
__global__ __launch_bounds__(256) void gemm_hmma(
    const float* __restrict__ A0, const float* __restrict__ A1, int chunksA,
    const __half* __restrict__ B0, const __half* __restrict__ B1, int chunksTot,
    const float* __restrict__ bias, void* __restrict__ Cout, int M)
{
    __shared__ __align__(128) union {
        struct { __half A[128][72]; __half B[64][72]; } ld;  // 27648 B
        float C[128][72];                                    // 36864 B
    } sm;

    const int tid = threadIdx.x;
    const int wid = tid >> 5;
    const int wm = (wid & 3) * 32;       // 4 m-warps
    const int wn = (wid >> 2) * 32;      // 2 n-warps
    const int mbase = blockIdx.y * 128;
    const int ncol0 = blockIdx.x * 64;

    wmma::fragment<wmma::accumulator, 16, 16, 16, float> acc[2][2];
#pragma unroll
    for (int i = 0; i < 2; i++)
#pragma unroll
        for (int j = 0; j < 2; j++) wmma::fill_fragment(acc[i][j], 0.f);

    for (int c = 0; c < chunksTot; ++c) {
        const float* Ap; const __half* Bp; int kloc;
        if (c < chunksA) { Ap = A0; Bp = B0; kloc = c * 64; }
        else             { Ap = A1; Bp = B1; kloc = (c - chunksA) * 64; }

        // A tile: 128 rows x 64 f32, convert to half (2048 float4 loads)
#pragma unroll
        for (int i = tid; i < 2048; i += 256) {
            const int row = i >> 4, j = i & 15;
            const int grow = mbase + row;
            float4 v = make_float4(0.f, 0.f, 0.f, 0.f);
            if (grow < M) v = *(const float4*)&Ap[(size_t)grow * KSTRIDE + kloc + j * 4];
            *(__half2*)&sm.ld.A[row][j * 4]     = __floats2half2_rn(v.x, v.y);
            *(__half2*)&sm.ld.A[row][j * 4 + 2] = __floats2half2_rn(v.z, v.w);
        }
        // B tile: 64 K-major rows x 64 halves (128 B/row = 8 int4)
#pragma unroll
        for (int i = tid; i < 512; i += 256) {
            const int row = i >> 3, j = i & 7;
            int4 v = *(const int4*)&Bp[(size_t)(ncol0 + row) * KSTRIDE + kloc + j * 8];
            *(int4*)&sm.ld.B[row][j * 8] = v;
        }
        __syncthreads();

#pragma unroll
        for (int kk = 0; kk < 64; kk += 16) {
            wmma::fragment<wmma::matrix_a, 16, 16, 16, __half, wmma::row_major> a0, a1;
            wmma::fragment<wmma::matrix_b, 16, 16, 16, __half, wmma::col_major> b0, b1;
            wmma::load_matrix_sync(a0, &sm.ld.A[wm][kk], 72);
            wmma::load_matrix_sync(a1, &sm.ld.A[wm + 16][kk], 72);
            wmma::load_matrix_sync(b0, &sm.ld.B[wn][kk], 72);
            wmma::load_matrix_sync(b1, &sm.ld.B[wn + 16][kk], 72);
            wmma::mma_sync(acc[0][0], a0, b0, acc[0][0]);
            wmma::mma_sync(acc[0][1], a0, b1, acc[0][1]);
            wmma::mma_sync(acc[1][0], a1, b0, acc[1][0]);
            wmma::mma_sync(acc[1][1], a1, b1, acc[1][1]);
        }
        __syncthreads();
    }

    // epilogue via SMEM
    wmma::store_matrix_sync(&sm.C[wm][wn],           acc[0][0], 72, wmma::mem_row_major);
    wmma::store_matrix_sync(&sm.C[wm][wn + 16],      acc[0][1], 72, wmma::mem_row_major);
    wmma::store_matrix_sync(&sm.C[wm + 16][wn],      acc[1][0], 72, wmma::mem_row_major);
    wmma::store_matrix_sync(&sm.C[wm + 16][wn + 16], acc[1][1], 72, wmma::mem_row_major);
    __syncthreads();

#pragma unroll
    for (int i = tid; i < 128 * 16; i += 256) {
        const int row = i >> 4, j = i & 15;
        const int grow = mbase + row;
        if (grow < M) {
            const int col = ncol0 + j * 4;
            float4 v = *(const float4*)&sm.C[row][j * 4];
            if (bias) {
                v.x += bias[col + 0]; v.y += bias[col + 1];
                v.z += bias[col + 2]; v.w += bias[col + 3];
            }
            if (EPI == 0) {
                *(float4*)((float*)Cout + (size_t)grow * NT + col) = v;
            } else {
                __half* Cp = (__half*)Cout + (size_t)grow * NT + col;
                *(__half2*)(Cp)     = __floats2half2_rn(v.x, v.y);
                *(__half2*)(Cp + 2) = __floats2half2_rn(v.z, v.w);
            }
        }
    }
}

// ---------------------------------------------------------------------------
// Transpose fp32 -> half, K-major:  out[C][R] = half(in[R][C])
// ---------------------------------------------------------------------------
__global__ void transpose_h_kernel(const float* __restrict__ in, __half* __restrict__ out,
                                   int R, int C)
{
    __shared__ float t[32][33];
    int bx = blockIdx.x * 32, by = blockIdx.y * 32;
    int x = bx + threadIdx.x;
#pragma unroll
    for (int i = 0; i < 32; i += 8) {
        int y = by + threadIdx.y + i;
        if (x < C && y < R) t[threadIdx.y + i][threadIdx.x] = in[(size_t)y * C + x];
    }
    __syncthreads();
    int x2 = by + threadIdx.x;
#pragma unroll
    for (int i = 0; i < 32; i += 8) {
        int y2 = bx + threadIdx.y + i;
        if (x2 < R && y2 < C) out[(size_t)y2 * R + x2] = __float2half(t[threadIdx.x][threadIdx.y + i]);
    }
}

// ---------------------------------------------------------------------------
// bf[j] = b_agg[j] + sum_m b_o[m] * (W_agg[m][j] + W_agg[m+256][j])
// ---------------------------------------------------------------------------
__global__ void fuse_bias_kernel(const float* __restrict__ b_o,
                                 const float* __restrict__ b_agg,
                                 const float* __restrict__ W_agg,
                                 float* __restrict__ bf)
{
    int j = threadIdx.x;
    float s = b_agg[j];
    for (int m = 0; m < DMODEL; m++)
        s += b_o[m] * (W_agg[(size_t)m * DMODEL + j] +
                       W_agg[(size_t)(m + DMODEL) * DMODEL + j]);
    bf[j] = s;
}

// ---------------------------------------------------------------------------
// Joint softmax over 32 = concat(aw0[16], aw1[16]) per (n,q,h); in-place.
// ---------------------------------------------------------------------------
__global__ void softmax_kernel(float* __restrict__ aw0, float* __restrict__ aw1,
                               int total)
{
    int t = blockIdx.x * blockDim.x + threadIdx.x;
    if (t >= total) return;
    float4* p0 = (float4*)(aw0 + (size_t)t * 16);
    float4* p1 = (float4*)(aw1 + (size_t)t * 16);
    float v[32];
    float4 r;
#pragma unroll
    for (int i = 0; i < 4; i++) {
        r = p0[i]; v[i*4+0]=r.x; v[i*4+1]=r.y; v[i*4+2]=r.z; v[i*4+3]=r.w;
    }
#pragma unroll
    for (int i = 0; i < 4; i++) {
        r = p1[i]; v[16+i*4+0]=r.x; v[16+i*4+1]=r.y; v[16+i*4+2]=r.z; v[16+i*4+3]=r.w;
    }
    float mx = v[0];
#pragma unroll
    for (int i = 1; i < 32; i++) mx = fmaxf(mx, v[i]);
    float sum = 0.f;
#pragma unroll
    for (int i = 0; i < 32; i++) { v[i] = expf(v[i] - mx); sum += v[i]; }
    float inv = 1.f / sum;
#pragma unroll
    for (int i = 0; i < 32; i++) v[i] *= inv;
#pragma unroll
    for (int i = 0; i < 4; i++)
        p0[i] = make_float4(v[i*4+0], v[i*4+1], v[i*4+2], v[i*4+3]);
#pragma unroll
    for (int i = 0; i < 4; i++)
        p1[i] = make_float4(v[16+i*4+0], v[16+i*4+1], v[16+i*4+2], v[16+i*4+3]);
}

// ---------------------------------------------------------------------------
// Deformable sampling: one warp per (n,q,h); lane = channel; value in fp16.
// ---------------------------------------------------------------------------
__global__ __launch_bounds__(256) void sample_kernel(
    const __half* __restrict__ value, const float* __restrict__ ref,
    const float* __restrict__ off, const float* __restrict__ attn,
    const int* __restrict__ shapes, const int* __restrict__ starts,
    float* __restrict__ out)
{
    int gwarp = (blockIdx.x * blockDim.x + threadIdx.x) >> 5;
    int lane = threadIdx.x & 31;
    if (gwarp >= NROWS * NHEADS) return;

    int h = gwarp & 7;
    int nq = gwarp >> 3;
    int n = nq / LQ;

    float my_off  = off[((size_t)nq * NHEADS + h) * 32 + lane];
    float my_attn = (lane < 16) ? attn[((size_t)nq * NHEADS + h) * 16 + lane] : 0.f;
    float my_ref  = (lane < 8)  ? ref[(size_t)nq * 8 + lane] : 0.f;

    float acc = 0.f;

#pragma unroll
    for (int l = 0; l < NLEV; l++) {
        int H = shapes[l * 2 + 0];
        int W = shapes[l * 2 + 1];
        int s = starts[l];
        float fW = (float)W, fH = (float)H;
        float rx = __shfl_sync(0xFFFFFFFFu, my_ref, l * 2 + 0);
        float ry = __shfl_sync(0xFFFFFFFFu, my_ref, l * 2 + 1);
        const __half* vbase =
            value + (((size_t)n * LQ + s) * NHEADS + h) * HDIM + lane;

#pragma unroll
        for (int p = 0; p < NPTS; p++) {
            int sp = l * 4 + p;
            float ox = __shfl_sync(0xFFFFFFFFu, my_off, sp * 2 + 0);
            float oy = __shfl_sync(0xFFFFFFFFu, my_off, sp * 2 + 1);
            float a  = __shfl_sync(0xFFFFFFFFu, my_attn, sp);

            // match reference arithmetic order exactly
            float x = (rx + ox / fW) * fW - 0.5f;
            float y = (ry + oy / fH) * fH - 0.5f;
            float x0f = floorf(x), y0f = floorf(y);
            int x0 = (int)x0f, y0 = (int)y0f;
            float lx = x - x0f, ly = y - y0f;
            float hx = 1.f - lx, hy = 1.f - ly;

            float smp = 0.f;
            bool xin0 = (x0 >= 0) & (x0 < W);
            bool xin1 = (x0 + 1 >= 0) & (x0 + 1 < W);
            bool yin0 = (y0 >= 0) & (y0 < H);
            bool yin1 = (y0 + 1 >= 0) & (y0 + 1 < H);
            if (xin0 & yin0) smp = fmaf(hy * hx, __half2float(__ldg(&vbase[(size_t)(y0 * W + x0) * DMODEL])), smp);
            if (xin1 & yin0) smp = fmaf(hy * lx, __half2float(__ldg(&vbase[(size_t)(y0 * W + x0 + 1) * DMODEL])), smp);
            if (xin0 & yin1) smp = fmaf(ly * hx, __half2float(__ldg(&vbase[(size_t)((y0 + 1) * W + x0) * DMODEL])), smp);
            if (xin1 & yin1) smp = fmaf(ly * lx, __half2float(__ldg(&vbase[(size_t)((y0 + 1) * W + x0 + 1) * DMODEL])), smp);
            acc = fmaf(a, smp, acc);
        }
    }

    out[(size_t)nq * DMODEL + h * HDIM + lane] = acc;
}

// ---------------------------------------------------------------------------
// Launcher
// ---------------------------------------------------------------------------
extern "C" void kernel_launch(void* const* d_in, const int* in_sizes, int n_in,
                              void* d_out, int out_size)
{
    const float* q0     = (const float*)d_in[0];
    const float* q1     = (const float*)d_in[1];
    const float* ref    = (const float*)d_in[2];
    const float* flat0  = (const float*)d_in[3];
    const float* flat1  = (const float*)d_in[4];
    const int*   shapes = (const int*)  d_in[5];
    const int*   starts = (const int*)  d_in[6];
    const float* W_so   = (const float*)d_in[7];
    const float* b_so   = (const float*)d_in[8];
    const float* W_aw   = (const float*)d_in[9];
    const float* b_aw   = (const float*)d_in[10];
    const float* W_v    = (const float*)d_in[11];
    const float* b_v    = (const float*)d_in[12];
    const float* W_o    = (const float*)d_in[13];
    const float* b_o    = (const float*)d_in[14];
    const float* W_agg  = (const float*)d_in[15];
    const float* b_agg  = (const float*)d_in[16];
    float* out = (float*)d_out;

    __half *value0, *value1, *Whv, *Whso, *Whaw, *Whf0, *Whf1;
    float *off0, *off1, *aw0, *aw1, *dd0, *dd1, *Wf0, *Wf1, *bf;
    cudaGetSymbolAddress((void**)&value0, g_value0);
    cudaGetSymbolAddress((void**)&value1, g_value1);
    cudaGetSymbolAddress((void**)&off0, g_off0);
    cudaGetSymbolAddress((void**)&off1, g_off1);
    cudaGetSymbolAddress((void**)&aw0, g_aw0);
    cudaGetSymbolAddress((void**)&aw1, g_aw1);
    cudaGetSymbolAddress((void**)&dd0, g_d0);
    cudaGetSymbolAddress((void**)&dd1, g_d1);
    cudaGetSymbolAddress((void**)&Wf0, g_Wf0);
    cudaGetSymbolAddress((void**)&Wf1, g_Wf1);
    cudaGetSymbolAddress((void**)&Whv, g_Whv);
    cudaGetSymbolAddress((void**)&Whso, g_Whso);
    cudaGetSymbolAddress((void**)&Whaw, g_Whaw);
    cudaGetSymbolAddress((void**)&Whf0, g_Whf0);
    cudaGetSymbolAddress((void**)&Whf1, g_Whf1);
    cudaGetSymbolAddress((void**)&bf, g_bf);

    dim3 blk(256);
    dim3 tblk(32, 8);
    const int MT = (NROWS + 127) / 128;   // 306

    // Launches 1-5 (prep), so launch #6 — the one ncu profiles (-s 5 -c 1) —
    // is the big fp16 value-projection GEMM.
    transpose_h_kernel<<<dim3(8, 8), tblk>>>(W_v,  Whv,  256, 256);   // 1
    transpose_h_kernel<<<dim3(8, 8), tblk>>>(W_so, Whso, 256, 256);   // 2
    transpose_h_kernel<<<dim3(4, 8), tblk>>>(W_aw, Whaw, 256, 128);   // 3
    sgemm_kernel<<<dim3(4, 2), blk>>>(W_o, W_agg,             nullptr, Wf0, 256, 256, 256); // 4
    sgemm_kernel<<<dim3(4, 2), blk>>>(W_o, W_agg + 256 * 256, nullptr, Wf1, 256, 256, 256); // 5

    // value projection (fp16 HMMA, fp16 output)                      // 6 <- profiled
    gemm_hmma<256, 1><<<dim3(4, MT), blk>>>(flat0, flat0, 4, Whv, Whv, 4, b_v, value0, NROWS);
    gemm_hmma<256, 1><<<dim3(4, MT), blk>>>(flat1, flat1, 4, Whv, Whv, 4, b_v, value1, NROWS);

    fuse_bias_kernel<<<1, DMODEL>>>(b_o, b_agg, W_agg, bf);
    transpose_h_kernel<<<dim3(8, 8), tblk>>>(Wf0, Whf0, 256, 256);
    transpose_h_kernel<<<dim3(8, 8), tblk>>>(Wf1, Whf1, 256, 256);

    // offset + attention-weight projections (fp16 HMMA)
    gemm_hmma<256, 0><<<dim3(4, MT), blk>>>(q0, q0, 4, Whso, Whso, 4, b_so, off0, NROWS);
    gemm_hmma<256, 0><<<dim3(4, MT), blk>>>(q1, q1, 4, Whso, Whso, 4, b_so, off1, NROWS);
    gemm_hmma<128, 0><<<dim3(2, MT), blk>>>(q0, q0, 4, Whaw, Whaw, 4, b_aw, aw0, NROWS);
    gemm_hmma<128, 0><<<dim3(2, MT), blk>>>(q1, q1, 4, Whaw, Whaw, 4, b_aw, aw1, NROWS);

    // joint softmax over 32
    {
        int total = NROWS * NHEADS;
        softmax_kernel<<<(total + 255) / 256, 256>>>(aw0, aw1, total);
    }

    // deformable sampling
    {
        int warps = NROWS * NHEADS;
        int blocks = (warps * 32 + 255) / 256;
        sample_kernel<<<blocks, 256>>>(value0, ref, off0, aw0, shapes, starts, dd0);
        sample_kernel<<<blocks, 256>>>(value1, ref, off1, aw1, shapes, starts, dd1);
    }

    // fused output projection: out = d0@Wf0^T + d1@Wf1^T + bf  (K=512)
    gemm_hmma<256, 0><<<dim3(4, MT), blk>>>(dd0, dd1, 4, Whf0, Whf1, 8, bf, out, NROWS);

    (void)in_sizes; (void)n_in; (void)out_size;
}